// round 2
// baseline (speedup 1.0000x reference)
#include <cuda_runtime.h>
#include <cstdint>

// Problem constants: B=64, S=512, A=8, D=128, C=1024
#define PB  64
#define PS  512
#define PA  8
#define PD  128

// Scratch: per-batch int accumulators, padded to 128B (32 ints) to spread L2 lines.
// Replay-safe: every launch leaves these at 0 (last block resets via atomicExch).
__device__ int          g_len[PB * 32];
__device__ unsigned int g_done = 0;

// ---------------------------------------------------------------------------
// Fused kernel: one warp per candidate (8 warps / block, all same batch).
//   - gather 128 fp32 (one float4/lane), scale by mask, streaming store
//   - lane 0 writes label/mask/loc
//   - block-level mask sum -> one RED per block into g_len[batch]
//   - last block (ticket) finalizes candidate_len + scalar, resets scratch
// ---------------------------------------------------------------------------
__global__ void __launch_bounds__(256)
cand_fused_kernel(const float*  __restrict__ word_repr,
                  const int*    __restrict__ anchor_cls,
                  const int*    __restrict__ anchor_loc,
                  const int*    __restrict__ cand_idx,
                  float*        __restrict__ out,
                  long long off_label,
                  long long off_mask,
                  long long off_loc,
                  long long off_len,
                  long long off_scalar,   // -1 if absent
                  float scalar_val,
                  int BC)
{
    __shared__ int s_mask[8];
    __shared__ int s_last;

    int wid  = threadIdx.x >> 5;
    int lane = threadIdx.x & 31;
    int warp = blockIdx.x * 8 + wid;   // candidate index

    int m_i = 0;
    if (warp < BC) {
        // All lanes read the same 3 ints -> L1 broadcast.
        int b = cand_idx[3 * warp + 0];
        int w = cand_idx[3 * warp + 1];
        int a = cand_idx[3 * warp + 2];

        long long flat = (((long long)b * PS + w) * PA + a);

        int l0 = anchor_loc[flat * 2 + 0];
        int l1 = anchor_loc[flat * 2 + 1];
        m_i = (l0 != l1) ? 1 : 0;
        float mask = (float)m_i;

        const float4* src = reinterpret_cast<const float4*>(word_repr + flat * PD);
        float4 v = src[lane];
        v.x *= mask; v.y *= mask; v.z *= mask; v.w *= mask;
        // Streaming store: don't pollute L2 (keep it for word_repr reads).
        __stcs(reinterpret_cast<float4*>(out + (long long)warp * PD) + lane, v);

        if (lane == 0) {
            out[off_label + warp]       = (float)anchor_cls[flat];
            out[off_mask  + warp]       = mask;
            out[off_loc + 2 * warp + 0] = (float)l0;
            out[off_loc + 2 * warp + 1] = (float)l1;
        }
    }

    if (lane == 0) s_mask[wid] = m_i;
    __syncthreads();

    if (threadIdx.x == 0) {
        int bsum = 0;
        #pragma unroll
        for (int i = 0; i < 8; i++) bsum += s_mask[i];
        // All 8 candidates of this block belong to one batch (1024 % 8 == 0).
        int batch = (blockIdx.x * 8) / 1024;   // = candidate / C
        atomicAdd(&g_len[batch * 32], bsum);
        __threadfence();
        unsigned int ticket = atomicAdd(&g_done, 1u);
        s_last = (ticket == gridDim.x - 1) ? 1 : 0;
    }
    __syncthreads();

    // Last block finalizes: read+reset accumulators, write len / scalar.
    if (s_last) {
        if (threadIdx.x < PB) {
            int v = atomicExch(&g_len[threadIdx.x * 32], 0);
            out[off_len + threadIdx.x] = fmaxf((float)v, 1.0f);
        }
        if (threadIdx.x == 0) {
            atomicExch(&g_done, 0u);
            if (off_scalar >= 0) out[off_scalar] = scalar_val;
        }
    }
}

// ---------------------------------------------------------------------------
// Host launcher
// ---------------------------------------------------------------------------
extern "C" void kernel_launch(void* const* d_in, const int* in_sizes, int n_in,
                              void* d_out, int out_size)
{
    const float* word_repr  = (const float*)d_in[0];  // (B,S,A,D) fp32
    const int*   anchor_cls = (const int*)d_in[1];    // (B,S,A)   int32
    const int*   anchor_loc = (const int*)d_in[2];    // (B,S,A,2) int32
    const int*   cand_idx   = (const int*)d_in[3];    // (B*C, 3)  int32
    float* out = (float*)d_out;

    int BC = in_sizes[3] / 3;          // 65536

    // Output tuple layout (reference return order):
    //   repr (B*C*D) | label (B*C) | [num (1)] | len (B) | mask (B*C) | loc (B*C*2)
    long long n_repr = (long long)BC * PD;
    long long total_with_scalar = n_repr + BC + 1 + PB + BC + 2LL * BC;

    long long off_label = n_repr;
    long long off_scalar, off_len;
    if ((long long)out_size >= total_with_scalar) {
        off_scalar = off_label + BC;
        off_len    = off_scalar + 1;
    } else {
        off_scalar = -1;
        off_len    = off_label + BC;
    }
    long long off_mask = off_len + PB;
    long long off_loc  = off_mask + BC;

    int threads = 256;                       // 8 warps = 8 candidates / block
    int blocks  = (BC + 7) / 8;              // 8192
    cand_fused_kernel<<<blocks, threads>>>(word_repr, anchor_cls, anchor_loc,
                                           cand_idx, out,
                                           off_label, off_mask, off_loc,
                                           off_len, off_scalar,
                                           (float)(BC / PB), BC);
}

// round 3
// speedup vs baseline: 1.5714x; 1.5714x over previous
#include <cuda_runtime.h>
#include <cstdint>

// Problem constants: B=64, S=512, A=8, D=128, C=1024
#define PB  64
#define PS  512
#define PA  8
#define PD  128

#define LEN_BLOCKS 64   // first LEN_BLOCKS blocks compute candidate_len

// ---------------------------------------------------------------------------
// One kernel, two independent roles (no cross-block communication):
//   blocks [0, 64):      candidate_len for batch b — reads cand_idx+anchor_loc
//                        directly from inputs, full reduction in-block.
//   blocks [64, 64+8192): gather — one warp per candidate, 8 warps/block.
// ---------------------------------------------------------------------------
__global__ void __launch_bounds__(256)
cand_kernel(const float*  __restrict__ word_repr,
            const int*    __restrict__ anchor_cls,
            const int*    __restrict__ anchor_loc,
            const int*    __restrict__ cand_idx,
            float*        __restrict__ out,
            long long off_label,
            long long off_mask,
            long long off_loc,
            long long off_len,
            long long off_scalar,   // -1 if absent
            float scalar_val,
            int BC, int C)
{
    if (blockIdx.x < LEN_BLOCKS) {
        // ---- len role: batch = blockIdx.x, reduce mask over C candidates ----
        __shared__ int smem[8];
        int batch = blockIdx.x;
        int base  = batch * C;

        int sum = 0;
        for (int i = threadIdx.x; i < C; i += blockDim.x) {
            int c = base + i;
            int b = cand_idx[3 * c + 0];
            int w = cand_idx[3 * c + 1];
            int a = cand_idx[3 * c + 2];
            long long flat = (((long long)b * PS + w) * PA + a);
            int2 loc = *reinterpret_cast<const int2*>(anchor_loc + flat * 2);
            sum += (loc.x != loc.y) ? 1 : 0;
        }
        #pragma unroll
        for (int o = 16; o > 0; o >>= 1)
            sum += __shfl_down_sync(0xFFFFFFFFu, sum, o);

        int lane = threadIdx.x & 31;
        int wid  = threadIdx.x >> 5;
        if (lane == 0) smem[wid] = sum;
        __syncthreads();
        if (threadIdx.x == 0) {
            int total = 0;
            #pragma unroll
            for (int i = 0; i < 8; i++) total += smem[i];
            out[off_len + batch] = fmaxf((float)total, 1.0f);
            if (batch == 0 && off_scalar >= 0)
                out[off_scalar] = scalar_val;
        }
        return;
    }

    // ---- gather role: one warp per candidate ----
    int wid  = threadIdx.x >> 5;
    int lane = threadIdx.x & 31;
    int warp = (blockIdx.x - LEN_BLOCKS) * 8 + wid;   // candidate index
    if (warp >= BC) return;

    // All lanes read the same 3 ints -> L1 broadcast.
    int b = cand_idx[3 * warp + 0];
    int w = cand_idx[3 * warp + 1];
    int a = cand_idx[3 * warp + 2];

    long long flat = (((long long)b * PS + w) * PA + a);

    int2 loc = *reinterpret_cast<const int2*>(anchor_loc + flat * 2);
    float mask = (loc.x != loc.y) ? 1.0f : 0.0f;

    const float4* src = reinterpret_cast<const float4*>(word_repr + flat * PD);
    float4 v = src[lane];
    v.x *= mask; v.y *= mask; v.z *= mask; v.w *= mask;
    reinterpret_cast<float4*>(out + (long long)warp * PD)[lane] = v;

    if (lane == 0) {
        out[off_label + warp]       = (float)anchor_cls[flat];
        out[off_mask  + warp]       = mask;
        out[off_loc + 2 * warp + 0] = (float)loc.x;
        out[off_loc + 2 * warp + 1] = (float)loc.y;
    }
}

// ---------------------------------------------------------------------------
// Host launcher
// ---------------------------------------------------------------------------
extern "C" void kernel_launch(void* const* d_in, const int* in_sizes, int n_in,
                              void* d_out, int out_size)
{
    const float* word_repr  = (const float*)d_in[0];  // (B,S,A,D) fp32
    const int*   anchor_cls = (const int*)d_in[1];    // (B,S,A)   int32
    const int*   anchor_loc = (const int*)d_in[2];    // (B,S,A,2) int32
    const int*   cand_idx   = (const int*)d_in[3];    // (B*C, 3)  int32
    float* out = (float*)d_out;

    int BC = in_sizes[3] / 3;          // 65536
    int C  = BC / PB;                  // 1024

    // Output tuple layout (reference return order):
    //   repr (B*C*D) | label (B*C) | [num (1)] | len (B) | mask (B*C) | loc (B*C*2)
    long long n_repr = (long long)BC * PD;
    long long total_with_scalar = n_repr + BC + 1 + PB + BC + 2LL * BC;

    long long off_label = n_repr;
    long long off_scalar, off_len;
    if ((long long)out_size >= total_with_scalar) {
        off_scalar = off_label + BC;
        off_len    = off_scalar + 1;
    } else {
        off_scalar = -1;
        off_len    = off_label + BC;
    }
    long long off_mask = off_len + PB;
    long long off_loc  = off_mask + BC;

    int threads = 256;                            // 8 warps = 8 candidates/block
    int blocks  = LEN_BLOCKS + (BC + 7) / 8;      // 64 + 8192
    cand_kernel<<<blocks, threads>>>(word_repr, anchor_cls, anchor_loc,
                                     cand_idx, out,
                                     off_label, off_mask, off_loc,
                                     off_len, off_scalar,
                                     (float)C, BC, C);
}